// round 14
// baseline (speedup 1.0000x reference)
#include <cuda_runtime.h>

// x: [8,16,256,256] f32 -> out: [8,64,256,256] f32
// One warp = one full image row (32 lanes x 8 px = 256 cols).
// Halos via warp shuffle; lanes 0/31 are true image edges (zero-pad selects).
// Epilogue ordered to free v before contrast; mean eliminated (|9v - s1| form).
// Block 32x8, grid (32,128). launch_bounds(256,5) -> 51-reg target, 5 blocks/SM.

#define HW 65536

__device__ __forceinline__ float frcp_approx(float a) {
    float r; asm("rcp.approx.f32 %0, %1;" : "=f"(r) : "f"(a)); return r;
}
__device__ __forceinline__ float frsqrt_approx(float a) {
    float r; asm("rsqrt.approx.f32 %0, %1;" : "=f"(r) : "f"(a)); return r;
}
__device__ __forceinline__ float flg2_approx(float a) {
    float r; asm("lg2.approx.f32 %0, %1;" : "=f"(r) : "f"(a)); return r;
}

__global__ __launch_bounds__(256, 5) void glcm_martingale_kernel(
    const float* __restrict__ x, float* __restrict__ out)
{
    const int img = blockIdx.y;                      // b*16+c
    const int h   = blockIdx.x * 8 + threadIdx.y;    // output row
    const int tx  = threadIdx.x;
    const int wb  = tx * 8;                          // aligned col base (0..248)
    const float* __restrict__ xin = x + (size_t)img * HW;

    // ---- own 8 columns, 3 rows (zero for OOB rows) ----
    float v[3][8];
#pragma unroll
    for (int r = 0; r < 3; r++) {
        const int gh = h - 1 + r;
        float4 a = make_float4(0.f, 0.f, 0.f, 0.f);
        float4 b = a;
        if ((unsigned)gh < 256u) {
            const float* __restrict__ row = xin + gh * 256 + wb;
            a = *(const float4*)row;
            b = *(const float4*)(row + 4);
        }
        v[r][0] = a.x; v[r][1] = a.y; v[r][2] = a.z; v[r][3] = a.w;
        v[r][4] = b.x; v[r][5] = b.y; v[r][6] = b.z; v[r][7] = b.w;
    }

    // ---- own column sums (lg2 entropy; ln2 folded into final constant) ----
    float c1[8], c2[8], ct[8];
#pragma unroll
    for (int j = 0; j < 8; j++) {
        const float v0 = v[0][j], v1 = v[1][j], v2 = v[2][j];
        c1[j] = v0 + v1 + v2;
        c2[j] = fmaf(v0, v0, fmaf(v1, v1, v2 * v2));
        ct[j] = v0 * flg2_approx(v0 + 1e-6f)
              + v1 * flg2_approx(v1 + 1e-6f)
              + v2 * flg2_approx(v2 + 1e-6f);  // 0*lg2(eps) = 0 matches zero-pad
    }

    // ---- halo columns via shuffle; lanes 0/31 are the zero-padded edges ----
    const unsigned FULL = 0xFFFFFFFFu;
    float vL0 = __shfl_up_sync(FULL, v[0][7], 1);
    float vL1 = __shfl_up_sync(FULL, v[1][7], 1);
    float vL2 = __shfl_up_sync(FULL, v[2][7], 1);
    float c1L = __shfl_up_sync(FULL, c1[7], 1);
    float c2L = __shfl_up_sync(FULL, c2[7], 1);
    float ctL = __shfl_up_sync(FULL, ct[7], 1);
    float vR0 = __shfl_down_sync(FULL, v[0][0], 1);
    float vR1 = __shfl_down_sync(FULL, v[1][0], 1);
    float vR2 = __shfl_down_sync(FULL, v[2][0], 1);
    float c1R = __shfl_down_sync(FULL, c1[0], 1);
    float c2R = __shfl_down_sync(FULL, c2[0], 1);
    float ctR = __shfl_down_sync(FULL, ct[0], 1);
    if (tx == 0)  { vL0 = vL1 = vL2 = 0.f; c1L = 0.f; c2L = 0.f; ctL = 0.f; }
    if (tx == 31) { vR0 = vR1 = vR2 = 0.f; c1R = 0.f; c2R = 0.f; ctR = 0.f; }

    // ---- extended 10-wide arrays (register renames under full unroll) ----
    const float C1[10] = {c1L, c1[0], c1[1], c1[2], c1[3], c1[4], c1[5], c1[6], c1[7], c1R};
    const float C2[10] = {c2L, c2[0], c2[1], c2[2], c2[3], c2[4], c2[5], c2[6], c2[7], c2R};
    const float CT[10] = {ctL, ct[0], ct[1], ct[2], ct[3], ct[4], ct[5], ct[6], ct[7], ctR};

    const float inv9  = 1.0f / 9.0f;
    const float inv81 = 1.0f / 81.0f;
    const float E   = 0.60653065971263342f;          // exp(-0.5)
    const float EE  = 1e-6f * E;
    const float E9  = E / 9.0f;
    const float CEn = -0.6931471805599453f * E9;     // -ln2 * E/9 (entropy)

    float* __restrict__ o = out + (size_t)img * 4 * HW + h * 256 + wb;
    float4 fa, fb;

    // ---- window sums; entropy & energy stored immediately (short live ranges) ----
    float s1[8], ss[8];
    {
        float s2[8], st[8];
#pragma unroll
        for (int k = 0; k < 8; k++) {
            s1[k] = C1[k] + C1[k + 1] + C1[k + 2];
            s2[k] = C2[k] + C2[k + 1] + C2[k + 2];
            st[k] = CT[k] + CT[k + 1] + CT[k + 2];
            ss[k] = fmaxf(fmaf(-s1[k] * inv9, s1[k], s2[k]), 0.0f);
        }
        // entropy plane (frees st)
#pragma unroll
        for (int k = 0; k < 4; k++) {
            (&fa.x)[k] = fmaf(st[k], CEn, EE);
            (&fb.x)[k] = fmaf(st[k + 4], CEn, EE);
        }
        *(float4*)(o + 2 * HW) = fa;
        *(float4*)(o + 2 * HW + 4) = fb;
        // energy plane (frees s2)
#pragma unroll
        for (int k = 0; k < 4; k++) {
            (&fa.x)[k] = fmaf(s2[k], E9, EE);
            (&fb.x)[k] = fmaf(s2[k + 4], E9, EE);
        }
        *(float4*)(o + HW) = fa;
        *(float4*)(o + HW + 4) = fb;
    }

    // ---- homogeneity BEFORE contrast: frees v (24 regs) early ----
    // sum|p - mean| = sum|9p - s1| / 9  ->  homog = 1/(1 + sum|9p-s1|/81)
    {
        const float V0[10] = {vL0, v[0][0], v[0][1], v[0][2], v[0][3], v[0][4], v[0][5], v[0][6], v[0][7], vR0};
        const float V1[10] = {vL1, v[1][0], v[1][1], v[1][2], v[1][3], v[1][4], v[1][5], v[1][6], v[1][7], vR1};
        const float V2[10] = {vL2, v[2][0], v[2][1], v[2][2], v[2][3], v[2][4], v[2][5], v[2][6], v[2][7], vR2};
#pragma unroll
        for (int k = 0; k < 8; k++) {
            const float s = s1[k];
            float dA0 = fmaf(9.f, V0[k], -s), dA1 = fmaf(9.f, V0[k+1], -s), dA2 = fmaf(9.f, V0[k+2], -s);
            float dB0 = fmaf(9.f, V1[k], -s), dB1 = fmaf(9.f, V1[k+1], -s), dB2 = fmaf(9.f, V1[k+2], -s);
            float dC0 = fmaf(9.f, V2[k], -s), dC1 = fmaf(9.f, V2[k+1], -s), dC2 = fmaf(9.f, V2[k+2], -s);
            float sA = fabsf(dA0) + fabsf(dA1) + fabsf(dA2);
            float sB = fabsf(dB0) + fabsf(dB1) + fabsf(dB2);
            float sC = fabsf(dC0) + fabsf(dC1) + fabsf(dC2);
            const float hmg = fmaf(frcp_approx(fmaf(sA + sB + sC, inv81, 1.0f)), E, EE);
            if (k < 4) (&fa.x)[k] = hmg; else (&fb.x)[k - 4] = hmg;
        }
        *(float4*)(o + 3 * HW) = fa;
        *(float4*)(o + 3 * HW + 4) = fb;
    }

    // ---- contrast last: 1/(sqrt(ss/8)+1e-6) ~ r0 - 1e-6*r0^2, r0 = rsqrt(ss/8)
#pragma unroll
    for (int k = 0; k < 8; k++) {
        const float r0 = frsqrt_approx(ss[k] * 0.125f);
        const float rs = fmaf(-1e-6f, r0 * r0, r0);
        const float c  = fmaf(ss[k] * E9, rs * rs, EE);
        if (k < 4) (&fa.x)[k] = c; else (&fb.x)[k - 4] = c;
    }
    *(float4*)o = fa;
    *(float4*)(o + 4) = fb;
}

extern "C" void kernel_launch(void* const* d_in, const int* in_sizes, int n_in,
                              void* d_out, int out_size)
{
    const float* x = (const float*)d_in[0];
    float* out = (float*)d_out;
    (void)in_sizes; (void)n_in; (void)out_size;

    dim3 block(32, 8);
    dim3 grid(32, 8 * 16);
    glcm_martingale_kernel<<<grid, block>>>(x, out);
}

// round 15
// speedup vs baseline: 1.3748x; 1.3748x over previous
#include <cuda_runtime.h>

// x: [8,16,256,256] f32 -> out: [8,64,256,256] f32
// R7 structure (best measured: 40 regs, occ 65%, issue 89%): each thread does
// 4 horizontal pixels, window loaded directly from global (L1-served overlap).
// Slot cuts only: raw lg2 entropy (ln2 folded), rsqrt contrast, mean-free
// homogeneity. No launch-bounds minimum. Block 32x8, grid (2,32,128).

#define HW 65536

__device__ __forceinline__ float frcp_approx(float a) {
    float r; asm("rcp.approx.f32 %0, %1;" : "=f"(r) : "f"(a)); return r;
}
__device__ __forceinline__ float frsqrt_approx(float a) {
    float r; asm("rsqrt.approx.f32 %0, %1;" : "=f"(r) : "f"(a)); return r;
}
__device__ __forceinline__ float flg2_approx(float a) {
    float r; asm("lg2.approx.f32 %0, %1;" : "=f"(r) : "f"(a)); return r;
}

__global__ __launch_bounds__(256) void glcm_martingale_kernel(
    const float* __restrict__ x, float* __restrict__ out)
{
    const int img = blockIdx.z;                         // b*16+c
    const int h   = blockIdx.y * 8 + threadIdx.y;       // output row
    const int wb  = blockIdx.x * 128 + threadIdx.x * 4; // aligned col base
    const float* __restrict__ xin = x + (size_t)img * HW;

    // ---- load 3x6 window: cols wb-1 .. wb+4 ----
    float v[3][6];
#pragma unroll
    for (int r = 0; r < 3; r++) {
        const int gh = h - 1 + r;
        float4 a = make_float4(0.f, 0.f, 0.f, 0.f);
        float vl = 0.f, vr = 0.f;
        if ((unsigned)gh < 256u) {
            const float* __restrict__ row = xin + gh * 256;
            a = *(const float4*)(row + wb);
            if (wb > 0)   vl = row[wb - 1];
            if (wb < 252) vr = row[wb + 4];
        }
        v[r][0] = vl;  v[r][1] = a.x; v[r][2] = a.y;
        v[r][3] = a.z; v[r][4] = a.w; v[r][5] = vr;
    }

    // ---- per-column sums (raw lg2; ln2 folded into entropy constant) ----
    float c1[6], c2[6], ct[6];
#pragma unroll
    for (int j = 0; j < 6; j++) {
        const float v0 = v[0][j], v1 = v[1][j], v2 = v[2][j];
        c1[j] = v0 + v1 + v2;
        c2[j] = fmaf(v0, v0, fmaf(v1, v1, v2 * v2));
        ct[j] = v0 * flg2_approx(v0 + 1e-6f)
              + v1 * flg2_approx(v1 + 1e-6f)
              + v2 * flg2_approx(v2 + 1e-6f);   // 0*lg2(eps) = 0 matches zero-pad
    }

    const float inv9  = 1.0f / 9.0f;
    const float inv81 = 1.0f / 81.0f;
    const float E   = 0.60653065971263342f;             // exp(-0.5)
    const float EE  = 1e-6f * E;
    const float E9  = E / 9.0f;
    const float CEn = -0.6931471805599453f * E9;        // -ln2 * E/9

    float* __restrict__ o = out + (size_t)img * 4 * HW + h * 256 + wb;
    float4 f;

    // ---- window sums; store entropy & energy immediately ----
    float s1[4], ss[4];
    {
        float s2[4], st[4];
#pragma unroll
        for (int k = 0; k < 4; k++) {
            s1[k] = c1[k] + c1[k + 1] + c1[k + 2];
            s2[k] = c2[k] + c2[k + 1] + c2[k + 2];
            st[k] = ct[k] + ct[k + 1] + ct[k + 2];
            ss[k] = fmaxf(fmaf(-s1[k] * inv9, s1[k], s2[k]), 0.0f);
        }
        // entropy plane (frees st)
#pragma unroll
        for (int k = 0; k < 4; k++) (&f.x)[k] = fmaf(st[k], CEn, EE);
        *(float4*)(o + 2 * HW) = f;
        // energy plane (frees s2)
#pragma unroll
        for (int k = 0; k < 4; k++) (&f.x)[k] = fmaf(s2[k], E9, EE);
        *(float4*)(o + HW) = f;
    }

    // ---- contrast: 1/(sqrt(ss/8)+1e-6) ~ r0 - 1e-6*r0^2, r0 = rsqrt(ss/8) ----
#pragma unroll
    for (int k = 0; k < 4; k++) {
        const float r0 = frsqrt_approx(ss[k] * 0.125f);
        const float rs = fmaf(-1e-6f, r0 * r0, r0);
        (&f.x)[k] = fmaf(ss[k] * E9, rs * rs, EE);
    }
    *(float4*)o = f;

    // ---- homogeneity: sum|p-mean| = sum|9p-s1|/9 -> 1/(1 + sum/81) ----
#pragma unroll
    for (int k = 0; k < 4; k++) {
        const float s = s1[k];
        float sA = 0.f, sB = 0.f, sC = 0.f;
#pragma unroll
        for (int j = 0; j < 3; j++) {
            sA += fabsf(fmaf(9.f, v[0][k + j], -s));
            sB += fabsf(fmaf(9.f, v[1][k + j], -s));
            sC += fabsf(fmaf(9.f, v[2][k + j], -s));
        }
        (&f.x)[k] = fmaf(frcp_approx(fmaf(sA + sB + sC, inv81, 1.0f)), E, EE);
    }
    *(float4*)(o + 3 * HW) = f;
}

extern "C" void kernel_launch(void* const* d_in, const int* in_sizes, int n_in,
                              void* d_out, int out_size)
{
    const float* x = (const float*)d_in[0];
    float* out = (float*)d_out;
    (void)in_sizes; (void)n_in; (void)out_size;

    dim3 block(32, 8);
    dim3 grid(2, 32, 8 * 16);
    glcm_martingale_kernel<<<grid, block>>>(x, out);
}